// round 5
// baseline (speedup 1.0000x reference)
#include <cuda_runtime.h>
#include <cstdint>

#define NSEQ 2048
#define DD 512
#define VV 512
#define CL 16

// ---------------- device scratch ----------------
static __device__ float g_X [NSEQ * DD];
static __device__ float g_XW[NSEQ * DD];
static __device__ float g_H [NSEQ * DD];
static __device__ float g_O [NSEQ * VV];
static __device__ float g_E [VV * VV];
static __device__ int   g_is64;

// ---------------- helpers ----------------
__device__ __forceinline__ uint32_t ctarank() {
    uint32_t r; asm("mov.u32 %0, %%cluster_ctarank;" : "=r"(r)); return r;
}
__device__ __forceinline__ uint32_t s2u(const void* p) {
    uint32_t a;
    asm("{ .reg .u64 t; cvta.to.shared.u64 t, %1; cvt.u32.u64 %0, t; }" : "=r"(a) : "l"(p));
    return a;
}
__device__ __forceinline__ uint32_t mapa_(uint32_t laddr, uint32_t r) {
    uint32_t a; asm("mapa.shared::cluster.u32 %0, %1, %2;" : "=r"(a) : "r"(laddr), "r"(r));
    return a;
}
// 128B bulk copy local smem -> remote CTA smem, complete_tx on remote mbarrier
__device__ __forceinline__ void bulk128(uint32_t rdst, uint32_t lsrc, uint32_t rmbar) {
    asm volatile("cp.async.bulk.shared::cluster.shared::cta.mbarrier::complete_tx::bytes [%0], [%1], 128, [%2];"
                 :: "r"(rdst), "r"(lsrc), "r"(rmbar) : "memory");
}
__device__ __forceinline__ void fence_async_() {
    asm volatile("fence.proxy.async.shared::cta;" ::: "memory");
}
__device__ __forceinline__ void mbar_init(uint32_t mb, uint32_t cnt) {
    asm volatile("mbarrier.init.shared.b64 [%0], %1;" :: "r"(mb), "r"(cnt) : "memory");
}
__device__ __forceinline__ void mbar_expect(uint32_t mb, uint32_t bytes) {
    asm volatile("mbarrier.arrive.expect_tx.shared.b64 _, [%0], %1;" :: "r"(mb), "r"(bytes) : "memory");
}
__device__ __forceinline__ void mbar_wait(uint32_t mb, uint32_t parity) {
    asm volatile(
        "{\n\t.reg .pred P;\n"
        "W%=:\n\t"
        "mbarrier.try_wait.parity.acquire.cluster.shared::cta.b64 P, [%0], %1, 0x989680;\n\t"
        "@!P bra W%=;\n\t}"
        :: "r"(mb), "r"(parity) : "memory");
}
__device__ __forceinline__ void cl_sync() {
    asm volatile("barrier.cluster.arrive.aligned;" ::: "memory");
    asm volatile("barrier.cluster.wait.aligned;"   ::: "memory");
}
__device__ __forceinline__ float wsum(float x) {
#pragma unroll
    for (int o = 16; o; o >>= 1) x += __shfl_xor_sync(0xffffffffu, x, o);
    return x;
}
__device__ __forceinline__ float ex2f_(float x) {
    float y; asm("ex2.approx.f32 %0, %1;" : "=f"(y) : "f"(x)); return y;
}
__device__ __forceinline__ float lg2f_(float x) {
    float y; asm("lg2.approx.f32 %0, %1;" : "=f"(y) : "f"(x)); return y;
}
__device__ __forceinline__ float rcpf_(float x) {
    float y; asm("rcp.approx.f32 %0, %1;" : "=f"(y) : "f"(x)); return y;
}
__device__ __forceinline__ float tanh_ex2(float x) {     // 1 - 2/(e^2x+1)
    float t = ex2f_(2.8853900817779268f * x);
    float r = rcpf_(t + 1.0f);
    return fmaf(-2.0f, r, 1.0f);
}

// ---------------- int64-vs-int32 index detection ----------------
__global__ void detect_kernel(const int* __restrict__ w) {
    __shared__ int any;
    if (threadIdx.x == 0) any = 0;
    __syncthreads();
    int acc = 0;
    for (int i = threadIdx.x; i < NSEQ / 2; i += blockDim.x) acc |= w[2 * i + 1];
    if (acc) atomicOr(&any, 1);
    __syncthreads();
    if (threadIdx.x == 0) g_is64 = (any == 0) ? 1 : 0;
}

// ---------------- embedding gather ----------------
__global__ void gather_kernel(const void* __restrict__ nums, const float* __restrict__ emb) {
    int t = blockIdx.x;
    long long idx = g_is64 ? ((const long long*)nums)[t]
                           : (long long)((const int*)nums)[t];
    const float4* src = (const float4*)(emb + (size_t)idx * DD);
    float4* dst = (float4*)(&g_X[(size_t)t * DD]);
    dst[threadIdx.x] = src[threadIdx.x];      // blockDim = 128
}

// ---------------- precompute E = exp(T) (base-2 weights) ----------------
__global__ void expT_kernel(const float* __restrict__ T) {
    int i = blockIdx.x * 256 + threadIdx.x;
    g_E[i] = ex2f_(T[i] * 1.4426950408889634f);
}

// ---------------- SIMT tiled SGEMM: C[2048,512] = A@B + bias ----------------
__global__ __launch_bounds__(256)
void gemm_bias(const float* __restrict__ A, const float* __restrict__ B,
               const float* __restrict__ bias, float* __restrict__ C)
{
    __shared__ __align__(16) float As[16][68];
    __shared__ __align__(16) float Bs[16][68];
    const int tid = threadIdx.x;
    const int bm = blockIdx.y * 64;
    const int bn = blockIdx.x * 64;
    const int tm = tid >> 4, tn = tid & 15;
    float acc[4][4] = {};
    for (int k0 = 0; k0 < 512; k0 += 16) {
        {
            int row = tid >> 2, cg = (tid & 3) * 4;
            float4 v = *(const float4*)(A + (size_t)(bm + row) * 512 + k0 + cg);
            As[cg + 0][row] = v.x; As[cg + 1][row] = v.y;
            As[cg + 2][row] = v.z; As[cg + 3][row] = v.w;
        }
        {
            int row = tid >> 4, col = (tid & 15) * 4;
            *(float4*)&Bs[row][col] = *(const float4*)(B + (size_t)(k0 + row) * 512 + bn + col);
        }
        __syncthreads();
#pragma unroll
        for (int k = 0; k < 16; k++) {
            float4 a = *(const float4*)&As[k][tm * 4];
            float4 b = *(const float4*)&Bs[k][tn * 4];
            float av[4] = {a.x, a.y, a.z, a.w};
            float bv[4] = {b.x, b.y, b.z, b.w};
#pragma unroll
            for (int i = 0; i < 4; i++)
#pragma unroll
                for (int jj = 0; jj < 4; jj++)
                    acc[i][jj] = fmaf(av[i], bv[jj], acc[i][jj]);
        }
        __syncthreads();
    }
    float4 bb = *(const float4*)(bias + bn + tn * 4);
#pragma unroll
    for (int i = 0; i < 4; i++) {
        float4 o;
        o.x = acc[i][0] + bb.x; o.y = acc[i][1] + bb.y;
        o.z = acc[i][2] + bb.z; o.w = acc[i][3] + bb.w;
        *(float4*)(C + (size_t)(bm + tm * 4 + i) * 512 + bn + tn * 4) = o;
    }
}

// State buffers are PLAIN contiguous [512] floats (bulk-copy friendly).
// Producer rank r's 32 outputs occupy words [32r, 32r+32) = one 128B block.
// Conflict-free read: lane reads float4 at [lane + 32*i], i=0..3 — every
// 8-lane LDS.128 phase covers banks 0..31 exactly once.
// k-index of hv[4i+j] = 128*i + 4*lane + j.

// ---------------- RNN recurrence: bulk-aggregated dataflow, 16-CTA cluster ----------------
__global__ void __launch_bounds__(512, 1)
rnn16(const float* __restrict__ Whh, const float* __restrict__ XW,
      float* __restrict__ Hout)
{
    __shared__ __align__(16) float sh[2 * 512];
    __shared__ __align__(16) float stg[2 * 32];
    __shared__ __align__(8) long long mbar[2];
    const int tid  = threadIdx.x;
    const int lane = tid & 31;
    const int w    = tid >> 5;
    const uint32_t rank = ctarank();
    const int j0 = (int)rank * 32 + 2 * w;

    float w0[16], w1[16];
#pragma unroll
    for (int i = 0; i < 4; i++)
#pragma unroll
        for (int j = 0; j < 4; j++) {
            int k = 128 * i + 4 * lane + j;
            w0[4 * i + j] = Whh[(size_t)k * DD + j0];
            w1[4 * i + j] = Whh[(size_t)k * DD + j0 + 1];
        }
    for (int i = tid; i < 2 * 512; i += 512) sh[i] = 0.0f;   // h0 = 0

    const uint32_t base = s2u(sh);
    const uint32_t stgb = s2u(stg);
    const uint32_t mb0  = s2u(&mbar[0]);
    if (tid == 0) {
        mbar_init(mb0, 1);     mbar_init(mb0 + 8, 1);
        mbar_expect(mb0, 2048); mbar_expect(mb0 + 8, 2048);
    }
    __syncthreads();
    cl_sync();

    uint32_t rdst = 0, rmb = 0;
    if (tid < CL) {                         // warp 0 lanes: one bulk per peer
        rdst = mapa_(base + rank * 128u, (uint32_t)tid);
        rmb  = mapa_(mb0, (uint32_t)tid);
    }

    float2 xw = *(const float2*)&XW[j0];

#pragma unroll 1
    for (int t = 0; t < NSEQ; t++) {
        const uint32_t p = (uint32_t)(t & 1);
        if (t) {
            mbar_wait(mb0 + 8 * p, (uint32_t)(((t - 1) >> 1) & 1));
            if (tid == 0) mbar_expect(mb0 + 8 * p, 2048);
        }
        const float4* cb = (const float4*)(sh + p * 512);
        float4 a = cb[lane], b = cb[lane + 32], c = cb[lane + 64], d = cb[lane + 96];
        float pa, pb, qa, qb;
        pa = a.x * w0[0];            qa = a.x * w1[0];
        pb = a.y * w0[1];            qb = a.y * w1[1];
        pa = fmaf(a.z, w0[2], pa);   qa = fmaf(a.z, w1[2], qa);
        pb = fmaf(a.w, w0[3], pb);   qb = fmaf(a.w, w1[3], qb);
        pa = fmaf(b.x, w0[4], pa);   qa = fmaf(b.x, w1[4], qa);
        pb = fmaf(b.y, w0[5], pb);   qb = fmaf(b.y, w1[5], qb);
        pa = fmaf(b.z, w0[6], pa);   qa = fmaf(b.z, w1[6], qa);
        pb = fmaf(b.w, w0[7], pb);   qb = fmaf(b.w, w1[7], qb);
        pa = fmaf(c.x, w0[8], pa);   qa = fmaf(c.x, w1[8], qa);
        pb = fmaf(c.y, w0[9], pb);   qb = fmaf(c.y, w1[9], qb);
        pa = fmaf(c.z, w0[10], pa);  qa = fmaf(c.z, w1[10], qa);
        pb = fmaf(c.w, w0[11], pb);  qb = fmaf(c.w, w1[11], qb);
        pa = fmaf(d.x, w0[12], pa);  qa = fmaf(d.x, w1[12], qa);
        pb = fmaf(d.y, w0[13], pb);  qb = fmaf(d.y, w1[13], qb);
        pa = fmaf(d.z, w0[14], pa);  qa = fmaf(d.z, w1[14], qa);
        pb = fmaf(d.w, w0[15], pb);  qb = fmaf(d.w, w1[15], qb);
        float ps = wsum(pa + pb);
        float qs = wsum(qa + qb);
        float h0 = tanh_ex2(xw.x + ps);
        float h1 = tanh_ex2(xw.y + qs);
        const uint32_t np = (uint32_t)((t + 1) & 1);
        if (lane == 0) {
            *(float2*)&stg[np * 32 + 2 * w] = make_float2(h0, h1);
            *(float2*)&Hout[(size_t)t * DD + j0] = make_float2(h0, h1);
        }
        __syncthreads();
        if (t + 1 < NSEQ) {
            if (tid < CL) {
                fence_async_();
                bulk128(rdst + np * 2048u, stgb + np * 128u, rmb + 8u * np);
            }
            xw = *(const float2*)&XW[(size_t)(t + 1) * DD + j0];
        }
    }
    cl_sync();
}

// ---------------- CRF backward: bulk-aggregated, exp(T)-factored ----------------
__global__ void __launch_bounds__(512, 1)
crf16(const float* __restrict__ O, float* __restrict__ out)
{
    __shared__ __align__(16) float sh[2 * 512];
    __shared__ __align__(16) float eb[512];
    __shared__ __align__(16) float stg[2 * 32];
    __shared__ __align__(8) long long mbar[2];
    const int tid  = threadIdx.x;
    const int lane = tid & 31;
    const int w    = tid >> 5;
    const uint32_t rank = ctarank();
    const int u0 = (int)rank * 32 + 2 * w;
    const float L2E = 1.4426950408889634f;
    const float LN2 = 0.6931471805599453f;

    float e0[16], e1[16];
#pragma unroll
    for (int i = 0; i < 4; i++)
#pragma unroll
        for (int j = 0; j < 4; j++) {
            int k = 128 * i + 4 * lane + j;
            e0[4 * i + j] = g_E[(size_t)u0 * VV + k];
            e1[4 * i + j] = g_E[(size_t)(u0 + 1) * VV + k];
        }
    for (int i = tid; i < 2 * 512; i += 512) sh[i] = -1.0e30f;

    const uint32_t base = s2u(sh);
    const uint32_t stgb = s2u(stg);
    const uint32_t mb0  = s2u(&mbar[0]);
    if (tid == 0) {
        sh[1] = O[(size_t)(NSEQ - 1) * VV + 1] * L2E;   // c_init[EOS] (log2 units)
        mbar_init(mb0, 1);     mbar_init(mb0 + 8, 1);
        mbar_expect(mb0, 2048); mbar_expect(mb0 + 8, 2048);
    }
    __syncthreads();
    cl_sync();

    uint32_t rdst = 0, rmb = 0;
    if (tid < CL) {
        rdst = mapa_(base + rank * 128u, (uint32_t)tid);
        rmb  = mapa_(mb0, (uint32_t)tid);
    }

    float2 ov = *(const float2*)&O[(size_t)(NSEQ - 2) * VV + u0];
    float o0 = ov.x * L2E, o1 = ov.y * L2E;

#pragma unroll 1
    for (int si = 0; si < NSEQ - 1; si++) {
        const uint32_t p = (uint32_t)(si & 1);
        if (si) {
            mbar_wait(mb0 + 8 * p, (uint32_t)(((si - 1) >> 1) & 1));
            if (tid == 0) mbar_expect(mb0 + 8 * p, 2048);
        }
        const float* cbuf = sh + p * 512;
        const float offc = cbuf[1];                    // c[EOS] (log2 units)
        eb[tid] = ex2f_(cbuf[tid] - offc);
        __syncthreads();

        const float4* ep = (const float4*)eb;
        float4 a = ep[lane], b = ep[lane + 32], c = ep[lane + 64], d = ep[lane + 96];
        float pa, pb, qa, qb;
        pa = a.x * e0[0];            qa = a.x * e1[0];
        pb = a.y * e0[1];            qb = a.y * e1[1];
        pa = fmaf(a.z, e0[2], pa);   qa = fmaf(a.z, e1[2], qa);
        pb = fmaf(a.w, e0[3], pb);   qb = fmaf(a.w, e1[3], qb);
        pa = fmaf(b.x, e0[4], pa);   qa = fmaf(b.x, e1[4], qa);
        pb = fmaf(b.y, e0[5], pb);   qb = fmaf(b.y, e1[5], qb);
        pa = fmaf(b.z, e0[6], pa);   qa = fmaf(b.z, e1[6], qa);
        pb = fmaf(b.w, e0[7], pb);   qb = fmaf(b.w, e1[7], qb);
        pa = fmaf(c.x, e0[8], pa);   qa = fmaf(c.x, e1[8], qa);
        pb = fmaf(c.y, e0[9], pb);   qb = fmaf(c.y, e1[9], qb);
        pa = fmaf(c.z, e0[10], pa);  qa = fmaf(c.z, e1[10], qa);
        pb = fmaf(c.w, e0[11], pb);  qb = fmaf(c.w, e1[11], qb);
        pa = fmaf(d.x, e0[12], pa);  qa = fmaf(d.x, e1[12], qa);
        pb = fmaf(d.y, e0[13], pb);  qb = fmaf(d.y, e1[13], qb);
        pa = fmaf(d.z, e0[14], pa);  qa = fmaf(d.z, e1[14], qa);
        pb = fmaf(d.w, e0[15], pb);  qb = fmaf(d.w, e1[15], qb);
        float s0 = wsum(pa + pb);
        float s1 = wsum(qa + qb);
        float cl0 = o0 + offc + lg2f_(s0);
        float cl1 = o1 + offc + lg2f_(s1);

        const uint32_t np = (uint32_t)((si + 1) & 1);
        if (si == NSEQ - 2) {
            if (rank == 0 && tid == 0) out[0] = cl0 * LN2;   // c0[BOS]
        } else if (lane == 0) {
            *(float2*)&stg[np * 32 + 2 * w] = make_float2(cl0, cl1);
        }
        __syncthreads();   // protects eb reuse + staging visibility
        if (si + 1 < NSEQ - 1) {
            if (tid < CL) {
                fence_async_();
                bulk128(rdst + np * 2048u, stgb + np * 128u, rmb + 8u * np);
            }
            int row = NSEQ - 3 - si;
            float2 onx = *(const float2*)&O[(size_t)row * VV + u0];
            o0 = onx.x * L2E; o1 = onx.y * L2E;
        }
    }
    cl_sync();
}

// ---------------- launch ----------------
extern "C" void kernel_launch(void* const* d_in, const int* in_sizes, int n_in,
                              void* d_out, int out_size)
{
    const void*  nums = d_in[0];
    const float* emb  = (const float*)d_in[1];
    const float* Wxh1 = (const float*)d_in[2];
    const float* Whh1 = (const float*)d_in[3];
    const float* b1   = (const float*)d_in[4];
    const float* Wxh2 = (const float*)d_in[5];
    const float* Whh2 = (const float*)d_in[6];
    const float* b2   = (const float*)d_in[7];
    const float* Wl   = (const float*)d_in[8];
    const float* bl   = (const float*)d_in[9];
    const float* Tm   = (const float*)d_in[10];
    float* out = (float*)d_out;

    float *X, *XW, *H, *O;
    cudaGetSymbolAddress((void**)&X,  g_X);
    cudaGetSymbolAddress((void**)&XW, g_XW);
    cudaGetSymbolAddress((void**)&H,  g_H);
    cudaGetSymbolAddress((void**)&O,  g_O);

    cudaFuncSetAttribute((const void*)rnn16, cudaFuncAttributeNonPortableClusterSizeAllowed, 1);
    cudaFuncSetAttribute((const void*)crf16, cudaFuncAttributeNonPortableClusterSizeAllowed, 1);

    detect_kernel<<<1, 256>>>((const int*)nums);
    gather_kernel<<<NSEQ, 128>>>(nums, emb);
    expT_kernel<<<VV * VV / 256, 256>>>(Tm);

    dim3 gg(512 / 64, NSEQ / 64);
    gemm_bias<<<gg, 256>>>(X, Wxh1, b1, XW);

    cudaLaunchConfig_t cfg = {};
    cfg.gridDim  = dim3(CL, 1, 1);
    cfg.blockDim = dim3(512, 1, 1);
    cfg.dynamicSmemBytes = 0;
    cfg.stream = 0;
    cudaLaunchAttribute at[1];
    at[0].id = cudaLaunchAttributeClusterDimension;
    at[0].val.clusterDim.x = CL;
    at[0].val.clusterDim.y = 1;
    at[0].val.clusterDim.z = 1;
    cfg.attrs = at;
    cfg.numAttrs = 1;

    cudaLaunchKernelEx(&cfg, rnn16, (const float*)Whh1, (const float*)XW, H);
    gemm_bias<<<gg, 256>>>(H, Wxh2, b2, XW);
    cudaLaunchKernelEx(&cfg, rnn16, (const float*)Whh2, (const float*)XW, H);
    gemm_bias<<<gg, 256>>>(H, Wl, bl, O);
    cudaLaunchKernelEx(&cfg, crf16, (const float*)O, out);
}